// round 3
// baseline (speedup 1.0000x reference)
#include <cuda_runtime.h>
#include <cuda_bf16.h>

#define T 128
#define N 1024
#define NBLK 128          // persistent blocks (<= 148 SMs, all co-resident)
#define NTHR 256          // 8 warps per block, warp = one row
#define LMBDA 0.01f

// ---------------- device scratch (no allocations allowed) ----------------
__device__ float    g_Fx[T * N];      // precomputed F @ x_t, layout [t][i]
__device__ float    g_Sx[T];          // precomputed sum(x_t)
__device__ float    g_S[3][N];        // triple-buffered column sums of row-scaled P
__device__ unsigned g_cnt[256];       // per-step barrier counters

// ---------------- prologue: zero scratch (fresh every launch/replay) -----
__global__ void init_kernel() {
    int tid = blockIdx.x * blockDim.x + threadIdx.x;
    if (tid < 3 * N) ((float*)g_S)[tid] = 0.0f;
    if (tid < 256) g_cnt[tid] = 0u;
}

// ---------------- prologue: Sx[t] = sum_j X[t][j] ------------------------
__global__ void sx_kernel(const float* __restrict__ X) {
    int t = blockIdx.x, l = threadIdx.x;
    float s = 0.0f;
    for (int k = l; k < N; k += 32) s += X[t * N + k];
    #pragma unroll
    for (int o = 16; o; o >>= 1) s += __shfl_xor_sync(0xFFFFFFFFu, s, o);
    if (l == 0) g_Sx[t] = s;
}

// ---------------- prologue: Fx[t][i] = sum_k F[i][k] * X[t][k] -----------
// smem-tiled 32x32, grid (32 i-tiles, 4 t-tiles), 256 threads
__global__ void gemm_fx(const float* __restrict__ F, const float* __restrict__ X) {
    __shared__ float Ft[32][33];
    __shared__ float Xt[32][33];
    int ib = blockIdx.x, tb = blockIdx.y;
    int tid = threadIdx.x;
    int il = tid & 31;        // local i
    int tg = tid >> 5;        // 0..7, t-group
    float acc[4] = {0.f, 0.f, 0.f, 0.f};
    for (int kk = 0; kk < N; kk += 32) {
        #pragma unroll
        for (int q = 0; q < 4; q++) {
            int idx = tid + 256 * q;       // 0..1023
            int r = idx >> 5, c = idx & 31;
            Ft[r][c] = F[(ib * 32 + r) * N + kk + c];
            Xt[r][c] = X[(tb * 32 + r) * N + kk + c];
        }
        __syncthreads();
        #pragma unroll
        for (int k = 0; k < 32; k++) {
            float f = Ft[il][k];
            #pragma unroll
            for (int m = 0; m < 4; m++)
                acc[m] = fmaf(f, Xt[tg + 8 * m][k], acc[m]);
        }
        __syncthreads();
    }
    #pragma unroll
    for (int m = 0; m < 4; m++)
        g_Fx[(tb * 32 + tg + 8 * m) * N + ib * 32 + il] = acc[m];
}

// ---------------- main persistent scan kernel ----------------------------
// State per warp-lane: Q[32] = P row (post row-scale, PRE pending column scale).
// True P = Q * c (columns). Per step:
//   1. build c from previous step's column sums S; stage x_t
//   2. fold c into Q while computing dot1 = P@x and dot2 = sum(P) (rowsum base)
//   3. out = Fx + dot1 ; rowsum = dot2 + lambda*out*Sx ; row scale r
//   4. Q = r*(Q + lambda*out*x)   (in registers)
//   5. column sums: smem transpose-reduce within block, red.global into S
//   6. one grid barrier (counter slot per step)
__global__ __launch_bounds__(NTHR, 1) void rf_main(const float* __restrict__ X,
                                                   float* __restrict__ out) {
    __shared__ float c_s[N];
    __shared__ float x_s[N];
    __shared__ float slice[8][N];   // 32 KB

    const int tid = threadIdx.x;
    const int w = tid >> 5;
    const int l = tid & 31;
    const int blk = blockIdx.x;
    const int row = blk * 8 + w;

    float Q[32];
    #pragma unroll
    for (int k = 0; k < 32; k++) Q[k] = 0.0f;

    for (int t = 0; t < T; t++) {
        // ---- phase 1: column scale + stage x_t -------------------------
        if (t == 0) {
            for (int j = tid; j < N; j += NTHR) {
                c_s[j] = 1.0f;
                x_s[j] = X[j];
            }
        } else {
            const int q = (t - 1) % 3;
            for (int j = tid; j < N; j += NTHR) {
                float Sv = g_S[q][j];
                c_s[j] = (Sv > 1.0f) ? (1.0f / Sv) : 1.0f;
                x_s[j] = X[t * N + j];
            }
            // zero slot (t+1)%3 (last read at t-1, next accumulated at t+1)
            const int z = (t + 1) % 3;
            if (tid < 8) g_S[z][blk * 8 + tid] = 0.0f;
        }
        __syncthreads();

        // ---- phase 2: fold column scale, compute both dots -------------
        float dot1 = 0.0f, dot2 = 0.0f;
        #pragma unroll
        for (int k = 0; k < 32; k++) {
            int j = (k << 5) | l;
            float p = Q[k] * c_s[j];
            Q[k] = p;
            dot1 = fmaf(p, x_s[j], dot1);
            dot2 += p;
        }
        #pragma unroll
        for (int o = 16; o; o >>= 1) {
            dot1 += __shfl_xor_sync(0xFFFFFFFFu, dot1, o);
            dot2 += __shfl_xor_sync(0xFFFFFFFFu, dot2, o);
        }

        const float outv = g_Fx[t * N + row] + dot1;
        if (l == 0) out[t * N + row] = outv;

        if (t < T - 1) {
            // ---- phase 3/4: row renorm + Hebbian update in registers ----
            float rowsum = dot2 + LMBDA * outv * g_Sx[t];
            float r = (rowsum > 1.0f) ? (1.0f / rowsum) : 1.0f;
            float ra = r * LMBDA * outv;
            #pragma unroll
            for (int k = 0; k < 32; k++) {
                int j = (k << 5) | l;
                Q[k] = fmaf(ra, x_s[j], r * Q[k]);
                slice[w][j] = Q[k];
            }
            __syncthreads();

            // ---- phase 5: block column reduce + global accumulate ------
            float4 a = make_float4(0.f, 0.f, 0.f, 0.f);
            #pragma unroll
            for (int ww = 0; ww < 8; ww++) {
                float4 v = *reinterpret_cast<const float4*>(&slice[ww][tid * 4]);
                a.x += v.x; a.y += v.y; a.z += v.z; a.w += v.w;
            }
            const int p3 = t % 3;
            atomicAdd(&g_S[p3][tid * 4 + 0], a.x);
            atomicAdd(&g_S[p3][tid * 4 + 1], a.y);
            atomicAdd(&g_S[p3][tid * 4 + 2], a.z);
            atomicAdd(&g_S[p3][tid * 4 + 3], a.w);
            __threadfence();
            __syncthreads();

            // ---- phase 6: grid barrier (slot per step) -----------------
            if (tid == 0) {
                atomicAdd(&g_cnt[t], 1u);
                volatile unsigned* c = &g_cnt[t];
                while (*c < (unsigned)NBLK) { __nanosleep(32); }
                __threadfence();
            }
            __syncthreads();
        }
    }
}

// ---------------- launch ---------------------------------------------------
extern "C" void kernel_launch(void* const* d_in, const int* in_sizes, int n_in,
                              void* d_out, int out_size) {
    // inputs [T*N]; in_in_fixed [N*N] (dead); out_in_fixed [N*N]
    const float* X = nullptr;
    const float* F = nullptr;
    for (int i = 0; i < n_in; i++) {
        if (in_sizes[i] == T * N && X == nullptr) X = (const float*)d_in[i];
        if (in_sizes[i] == N * N) F = (const float*)d_in[i];  // last N*N = out_in_fixed
    }
    float* out = (float*)d_out;

    init_kernel<<<6, 512>>>();
    sx_kernel<<<T, 32>>>(X);
    dim3 g(N / 32, T / 32);
    gemm_fx<<<g, 256>>>(F, X);
    rf_main<<<NBLK, NTHR>>>(X, out);
}

// round 4
// speedup vs baseline: 1.0594x; 1.0594x over previous
#include <cuda_runtime.h>
#include <cuda_bf16.h>

#define T 128
#define N 1024
#define NBLK 128          // persistent blocks (<= 148 SMs, all co-resident)
#define NTHR 256          // 8 warps per block, warp = one row
#define LMBDA 0.01f

// ---------------- device scratch (no allocations allowed) ----------------
__device__ float    g_Fx[T * N];      // precomputed F @ x_t, layout [t][i]
__device__ float    g_Sx[T];          // precomputed sum(x_t)
__device__ float    g_S[3][N];        // triple-buffered column sums of row-scaled P
__device__ unsigned g_cnt[256];       // per-step barrier counters

// ---- acquire/release primitives (no full membars needed) -----------------
__device__ __forceinline__ unsigned ld_acquire_gpu(const unsigned* p) {
    unsigned v;
    asm volatile("ld.acquire.gpu.global.u32 %0, [%1];" : "=r"(v) : "l"(p) : "memory");
    return v;
}
__device__ __forceinline__ void red_release_gpu(unsigned* p, unsigned v) {
    asm volatile("red.release.gpu.global.add.u32 [%0], %1;" :: "l"(p), "r"(v) : "memory");
}

// ---------------- prologue: zero scratch (fresh every launch/replay) -----
__global__ void init_kernel() {
    int tid = blockIdx.x * blockDim.x + threadIdx.x;
    if (tid < 3 * N) ((float*)g_S)[tid] = 0.0f;
    if (tid < 256) g_cnt[tid] = 0u;
}

// ---------------- prologue: Sx[t] = sum_j X[t][j] ------------------------
__global__ void sx_kernel(const float* __restrict__ X) {
    int t = blockIdx.x, l = threadIdx.x;
    float s = 0.0f;
    for (int k = l; k < N; k += 32) s += X[t * N + k];
    #pragma unroll
    for (int o = 16; o; o >>= 1) s += __shfl_xor_sync(0xFFFFFFFFu, s, o);
    if (l == 0) g_Sx[t] = s;
}

// ---------------- prologue: Fx[t][i] = sum_k F[i][k] * X[t][k] -----------
__global__ void gemm_fx(const float* __restrict__ F, const float* __restrict__ X) {
    __shared__ float Ft[32][33];
    __shared__ float Xt[32][33];
    int ib = blockIdx.x, tb = blockIdx.y;
    int tid = threadIdx.x;
    int il = tid & 31;
    int tg = tid >> 5;
    float acc[4] = {0.f, 0.f, 0.f, 0.f};
    for (int kk = 0; kk < N; kk += 32) {
        #pragma unroll
        for (int q = 0; q < 4; q++) {
            int idx = tid + 256 * q;
            int r = idx >> 5, c = idx & 31;
            Ft[r][c] = F[(ib * 32 + r) * N + kk + c];
            Xt[r][c] = X[(tb * 32 + r) * N + kk + c];
        }
        __syncthreads();
        #pragma unroll
        for (int k = 0; k < 32; k++) {
            float f = Ft[il][k];
            #pragma unroll
            for (int m = 0; m < 4; m++)
                acc[m] = fmaf(f, Xt[tg + 8 * m][k], acc[m]);
        }
        __syncthreads();
    }
    #pragma unroll
    for (int m = 0; m < 4; m++)
        g_Fx[(tb * 32 + tg + 8 * m) * N + ib * 32 + il] = acc[m];
}

// ---------------- main persistent scan kernel ----------------------------
__global__ __launch_bounds__(NTHR, 1) void rf_main(const float* __restrict__ X,
                                                   float* __restrict__ out) {
    __shared__ float c_s[N];
    __shared__ float x_s[N];
    __shared__ float slice[8][N];   // 32 KB

    const int tid = threadIdx.x;
    const int w = tid >> 5;
    const int l = tid & 31;
    const int blk = blockIdx.x;
    const int row = blk * 8 + w;

    float Q[32];
    #pragma unroll
    for (int k = 0; k < 32; k++) Q[k] = 0.0f;

    for (int t = 0; t < T; t++) {
        // ---- phase 1: column scale + stage x_t -------------------------
        if (t == 0) {
            for (int j = tid; j < N; j += NTHR) {
                c_s[j] = 1.0f;
                x_s[j] = X[j];
            }
        } else {
            const int q = (t - 1) % 3;
            for (int j = tid; j < N; j += NTHR) {
                float Sv = g_S[q][j];
                c_s[j] = (Sv > 1.0f) ? (1.0f / Sv) : 1.0f;
                x_s[j] = X[t * N + j];
            }
            // zero slot (t+1)%3 (last read at t-1, next accumulated at t+1)
            const int z = (t + 1) % 3;
            if (tid < 8) g_S[z][blk * 8 + tid] = 0.0f;
        }
        __syncthreads();

        // ---- phase 2: fold column scale, compute both dots -------------
        float dot1 = 0.0f, dot2 = 0.0f;
        #pragma unroll
        for (int k = 0; k < 32; k++) {
            int j = (k << 5) | l;
            float p = Q[k] * c_s[j];
            Q[k] = p;
            dot1 = fmaf(p, x_s[j], dot1);
            dot2 += p;
        }
        #pragma unroll
        for (int o = 16; o; o >>= 1) {
            dot1 += __shfl_xor_sync(0xFFFFFFFFu, dot1, o);
            dot2 += __shfl_xor_sync(0xFFFFFFFFu, dot2, o);
        }

        const float outv = g_Fx[t * N + row] + dot1;
        if (l == 0) out[t * N + row] = outv;

        if (t < T - 1) {
            // ---- phase 3/4: row renorm + Hebbian update in registers ----
            float rowsum = dot2 + LMBDA * outv * g_Sx[t];
            float r = (rowsum > 1.0f) ? (1.0f / rowsum) : 1.0f;
            float ra = r * LMBDA * outv;
            #pragma unroll
            for (int k = 0; k < 32; k++) {
                int j = (k << 5) | l;
                Q[k] = fmaf(ra, x_s[j], r * Q[k]);
                slice[w][j] = Q[k];
            }
            __syncthreads();

            // ---- phase 5: block column reduce + global accumulate ------
            float4 a = make_float4(0.f, 0.f, 0.f, 0.f);
            #pragma unroll
            for (int ww = 0; ww < 8; ww++) {
                float4 v = *reinterpret_cast<const float4*>(&slice[ww][tid * 4]);
                a.x += v.x; a.y += v.y; a.z += v.z; a.w += v.w;
            }
            const int p3 = t % 3;
            atomicAdd(&g_S[p3][tid * 4 + 0], a.x);
            atomicAdd(&g_S[p3][tid * 4 + 1], a.y);
            atomicAdd(&g_S[p3][tid * 4 + 2], a.z);
            atomicAdd(&g_S[p3][tid * 4 + 3], a.w);
            __syncthreads();  // all block's REDs issued before the release-arrive

            // ---- phase 6: grid barrier, release/acquire, no sleep ------
            // bar.sync (intra-CTA HB) -> tid0 red.release arrive ->
            // tid0 ld.acquire poll -> bar.sync  == grid.sync() pattern.
            if (tid == 0) {
                red_release_gpu(&g_cnt[t], 1u);
                while (ld_acquire_gpu(&g_cnt[t]) < (unsigned)NBLK) { }
            }
            __syncthreads();
        }
    }
}

// ---------------- launch ---------------------------------------------------
extern "C" void kernel_launch(void* const* d_in, const int* in_sizes, int n_in,
                              void* d_out, int out_size) {
    // inputs [T*N]; in_in_fixed [N*N] (dead); out_in_fixed [N*N]
    const float* X = nullptr;
    const float* F = nullptr;
    for (int i = 0; i < n_in; i++) {
        if (in_sizes[i] == T * N && X == nullptr) X = (const float*)d_in[i];
        if (in_sizes[i] == N * N) F = (const float*)d_in[i];  // last N*N = out_in_fixed
    }
    float* out = (float*)d_out;

    init_kernel<<<6, 512>>>();
    sx_kernel<<<T, 32>>>(X);
    dim3 g(N / 32, T / 32);
    gemm_fx<<<g, 256>>>(F, X);
    rf_main<<<NBLK, NTHR>>>(X, out);
}

// round 5
// speedup vs baseline: 1.3461x; 1.2707x over previous
#include <cuda_runtime.h>
#include <cuda_bf16.h>

#define T 128
#define N 1024
#define NBLK 128          // persistent blocks (<= 148 SMs, all co-resident)
#define NTHR 256          // 8 warps per block, warp = one row
#define NRED 8            // reducer blocks (blocks 0..7)
#define GRPS 128          // 128 column-groups of 8 columns
#define LMBDA 0.01f

// ---------------- device scratch (no allocations allowed) ----------------
__device__ float    g_Fx[T * N];              // precomputed F @ x_t, [t][i]
__device__ float    g_Sx[T];                  // precomputed sum(x_t)
__device__ float    g_part[GRPS * NBLK * 8];  // per-block column partial sums
__device__ float    g_c[N];                   // column scales for next step
__device__ unsigned g_cnt1[T];                // partials-ready counters
__device__ unsigned g_cnt2[T];                // c-ready counters

// ---- acquire/release primitives ------------------------------------------
__device__ __forceinline__ unsigned ld_acquire_gpu(const unsigned* p) {
    unsigned v;
    asm volatile("ld.acquire.gpu.global.u32 %0, [%1];" : "=r"(v) : "l"(p) : "memory");
    return v;
}
__device__ __forceinline__ void red_release_gpu(unsigned* p, unsigned v) {
    asm volatile("red.release.gpu.global.add.u32 [%0], %1;" :: "l"(p), "r"(v) : "memory");
}

// ---------------- prologue: zero counters (fresh every launch/replay) ----
__global__ void init_kernel() {
    int tid = blockIdx.x * blockDim.x + threadIdx.x;
    if (tid < T) { g_cnt1[tid] = 0u; g_cnt2[tid] = 0u; }
}

// ---------------- prologue: Sx[t] = sum_j X[t][j] ------------------------
__global__ void sx_kernel(const float* __restrict__ X) {
    int t = blockIdx.x, l = threadIdx.x;
    float s = 0.0f;
    for (int k = l; k < N; k += 32) s += X[t * N + k];
    #pragma unroll
    for (int o = 16; o; o >>= 1) s += __shfl_xor_sync(0xFFFFFFFFu, s, o);
    if (l == 0) g_Sx[t] = s;
}

// ---------------- prologue: Fx[t][i] = sum_k F[i][k] * X[t][k] -----------
__global__ void gemm_fx(const float* __restrict__ F, const float* __restrict__ X) {
    __shared__ float Ft[32][33];
    __shared__ float Xt[32][33];
    int ib = blockIdx.x, tb = blockIdx.y;
    int tid = threadIdx.x;
    int il = tid & 31;
    int tg = tid >> 5;
    float acc[4] = {0.f, 0.f, 0.f, 0.f};
    for (int kk = 0; kk < N; kk += 32) {
        #pragma unroll
        for (int q = 0; q < 4; q++) {
            int idx = tid + 256 * q;
            int r = idx >> 5, c = idx & 31;
            Ft[r][c] = F[(ib * 32 + r) * N + kk + c];
            Xt[r][c] = X[(tb * 32 + r) * N + kk + c];
        }
        __syncthreads();
        #pragma unroll
        for (int k = 0; k < 32; k++) {
            float f = Ft[il][k];
            #pragma unroll
            for (int m = 0; m < 4; m++)
                acc[m] = fmaf(f, Xt[tg + 8 * m][k], acc[m]);
        }
        __syncthreads();
    }
    #pragma unroll
    for (int m = 0; m < 4; m++)
        g_Fx[(tb * 32 + tg + 8 * m) * N + ib * 32 + il] = acc[m];
}

// ---------------- main persistent scan kernel ----------------------------
// Per-warp state: Q[32] = one row of P (row-scaled, pending column scale).
// Per step: fold c while computing dots -> out -> row renorm + Hebbian update
// in registers -> block column partials (coalesced STG, NO atomics) ->
// arrive cnt1 -> 8 reducer blocks build c -> arrive cnt2 -> all read c.
__global__ __launch_bounds__(NTHR, 1) void rf_main(const float* __restrict__ X,
                                                   float* __restrict__ out) {
    __shared__ float c_s[N];
    __shared__ float x_s[N];
    __shared__ float slice[8][N];   // 32 KB

    const int tid = threadIdx.x;
    const int w = tid >> 5;
    const int l = tid & 31;
    const int blk = blockIdx.x;
    const int row = blk * 8 + w;

    float Q[32];
    #pragma unroll
    for (int k = 0; k < 32; k++) Q[k] = 0.0f;

    // prestage x_0, c = 1
    for (int j = tid; j < N; j += NTHR) { x_s[j] = X[j]; c_s[j] = 1.0f; }
    __syncthreads();

    for (int t = 0; t < T; t++) {
        if (t > 0) {
            // c from reducers (ordered by cnt2 acquire at end of prev step)
            for (int j = tid; j < N; j += NTHR) c_s[j] = g_c[j];
            __syncthreads();
        }

        // ---- fold column scale, compute dot1 = P@x, dot2 = sum(P) -------
        float dot1 = 0.0f, dot2 = 0.0f;
        #pragma unroll
        for (int k = 0; k < 32; k++) {
            int j = (k << 5) | l;
            float p = Q[k] * c_s[j];
            Q[k] = p;
            dot1 = fmaf(p, x_s[j], dot1);
            dot2 += p;
        }
        #pragma unroll
        for (int o = 16; o; o >>= 1) {
            dot1 += __shfl_xor_sync(0xFFFFFFFFu, dot1, o);
            dot2 += __shfl_xor_sync(0xFFFFFFFFu, dot2, o);
        }

        const float outv = g_Fx[t * N + row] + dot1;
        if (l == 0) out[t * N + row] = outv;

        if (t < T - 1) {
            // ---- row renorm + Hebbian update in registers ---------------
            float rowsum = dot2 + LMBDA * outv * g_Sx[t];
            float r = (rowsum > 1.0f) ? (1.0f / rowsum) : 1.0f;
            float ra = r * LMBDA * outv;
            #pragma unroll
            for (int k = 0; k < 32; k++) {
                int j = (k << 5) | l;
                Q[k] = fmaf(ra, x_s[j], r * Q[k]);
                slice[w][j] = Q[k];
            }
            __syncthreads();

            // ---- block column partials: coalesced STG.128, no atomics ---
            float4 a = make_float4(0.f, 0.f, 0.f, 0.f);
            #pragma unroll
            for (int ww = 0; ww < 8; ww++) {
                float4 v = *reinterpret_cast<const float4*>(&slice[ww][tid * 4]);
                a.x += v.x; a.y += v.y; a.z += v.z; a.w += v.w;
            }
            {
                const int grp  = tid >> 1;          // j-group = (tid*4)/8
                const int half = (tid & 1) * 4;
                *reinterpret_cast<float4*>(&g_part[(grp * NBLK + blk) * 8 + half]) = a;
            }
            __syncthreads();                        // all partials issued
            if (tid == 0) red_release_gpu(&g_cnt1[t], 1u);

            // ---- overlap: stage x_{t+1} while waiting -------------------
            for (int j = tid; j < N; j += NTHR) x_s[j] = X[(t + 1) * N + j];

            // ---- stage 2: 8 reducer blocks build c ----------------------
            if (blk < NRED) {
                if (tid == 0) {
                    while (ld_acquire_gpu(&g_cnt1[t]) < (unsigned)NBLK) { }
                }
                __syncthreads();   // acquire by tid0 + bar orders the reads
                #pragma unroll
                for (int gg = 0; gg < 2; gg++) {
                    const int g = blk * 16 + w * 2 + gg;
                    float acc[8] = {0.f,0.f,0.f,0.f,0.f,0.f,0.f,0.f};
                    #pragma unroll
                    for (int cch = 0; cch < 4; cch++) {
                        const float4* p = reinterpret_cast<const float4*>(
                            &g_part[(g * NBLK + (l + 32 * cch)) * 8]);
                        float4 v0 = p[0], v1 = p[1];
                        acc[0] += v0.x; acc[1] += v0.y; acc[2] += v0.z; acc[3] += v0.w;
                        acc[4] += v1.x; acc[5] += v1.y; acc[6] += v1.z; acc[7] += v1.w;
                    }
                    #pragma unroll
                    for (int o = 16; o; o >>= 1) {
                        #pragma unroll
                        for (int m = 0; m < 8; m++)
                            acc[m] += __shfl_xor_sync(0xFFFFFFFFu, acc[m], o);
                    }
                    if (l == 0) {
                        float4 c0, c1;
                        c0.x = (acc[0] > 1.0f) ? (1.0f / acc[0]) : 1.0f;
                        c0.y = (acc[1] > 1.0f) ? (1.0f / acc[1]) : 1.0f;
                        c0.z = (acc[2] > 1.0f) ? (1.0f / acc[2]) : 1.0f;
                        c0.w = (acc[3] > 1.0f) ? (1.0f / acc[3]) : 1.0f;
                        c1.x = (acc[4] > 1.0f) ? (1.0f / acc[4]) : 1.0f;
                        c1.y = (acc[5] > 1.0f) ? (1.0f / acc[5]) : 1.0f;
                        c1.z = (acc[6] > 1.0f) ? (1.0f / acc[6]) : 1.0f;
                        c1.w = (acc[7] > 1.0f) ? (1.0f / acc[7]) : 1.0f;
                        *reinterpret_cast<float4*>(&g_c[g * 8])     = c0;
                        *reinterpret_cast<float4*>(&g_c[g * 8 + 4]) = c1;
                    }
                }
                __syncthreads();                    // all c stores issued
                if (tid == 0) red_release_gpu(&g_cnt2[t], 1u);
            }

            // ---- wait for c (target = 8, light contention) --------------
            if (tid == 0) {
                while (ld_acquire_gpu(&g_cnt2[t]) < (unsigned)NRED) { }
            }
            __syncthreads();
        }
    }
}

// ---------------- launch ---------------------------------------------------
extern "C" void kernel_launch(void* const* d_in, const int* in_sizes, int n_in,
                              void* d_out, int out_size) {
    // inputs [T*N]; in_in_fixed [N*N] (dead); out_in_fixed [N*N]
    const float* X = nullptr;
    const float* F = nullptr;
    for (int i = 0; i < n_in; i++) {
        if (in_sizes[i] == T * N && X == nullptr) X = (const float*)d_in[i];
        if (in_sizes[i] == N * N) F = (const float*)d_in[i];  // last N*N = out_in_fixed
    }
    float* out = (float*)d_out;

    init_kernel<<<1, 256>>>();
    sx_kernel<<<T, 32>>>(X);
    dim3 g(N / 32, T / 32);
    gemm_fx<<<g, 256>>>(F, X);
    rf_main<<<NBLK, NTHR>>>(X, out);
}

// round 7
// speedup vs baseline: 1.6557x; 1.2300x over previous
#include <cuda_runtime.h>
#include <cuda_bf16.h>

#define T 128
#define N 1024
#define NBLK 128          // persistent blocks, all co-resident
#define NTHR 256          // 8 warps per block, warp = one row
#define LMBDA 0.01f

// ---------------- device scratch (no allocations allowed) ----------------
__device__ float    g_Fx[T * N];              // precomputed F @ x_t, [t][i]
__device__ float    g_Sx[T];                  // precomputed sum(x_t)
__device__ float    g_part[NBLK * NBLK * 8];  // [grp][blk][8] column partials
__device__ float    g_c[N];                   // column scales
__device__ unsigned g_cnt1;                   // monotonic: partials ready
__device__ unsigned g_cnt2;                   // monotonic: c ready

// ---- acquire/release primitives ------------------------------------------
__device__ __forceinline__ unsigned ld_acquire_gpu(const unsigned* p) {
    unsigned v;
    asm volatile("ld.acquire.gpu.global.u32 %0, [%1];" : "=r"(v) : "l"(p) : "memory");
    return v;
}
__device__ __forceinline__ void red_release_gpu(unsigned* p, unsigned v) {
    asm volatile("red.release.gpu.global.add.u32 [%0], %1;" :: "l"(p), "r"(v) : "memory");
}

// ---------------- prologue: zero counters (fresh every launch/replay) ----
__global__ void init_kernel() {
    if (threadIdx.x == 0) { g_cnt1 = 0u; g_cnt2 = 0u; }
}

// ---------------- prologue: Sx[t] = sum_j X[t][j] ------------------------
__global__ void sx_kernel(const float* __restrict__ X) {
    int t = blockIdx.x, l = threadIdx.x;
    float s = 0.0f;
    for (int k = l; k < N; k += 32) s += X[t * N + k];
    #pragma unroll
    for (int o = 16; o; o >>= 1) s += __shfl_xor_sync(0xFFFFFFFFu, s, o);
    if (l == 0) g_Sx[t] = s;
}

// ---------------- prologue: Fx[t][i] = sum_k F[i][k] * X[t][k] -----------
__global__ void gemm_fx(const float* __restrict__ F, const float* __restrict__ X) {
    __shared__ float Ft[32][33];
    __shared__ float Xt[32][33];
    int ib = blockIdx.x, tb = blockIdx.y;
    int tid = threadIdx.x;
    int il = tid & 31;
    int tg = tid >> 5;
    float acc[4] = {0.f, 0.f, 0.f, 0.f};
    for (int kk = 0; kk < N; kk += 32) {
        #pragma unroll
        for (int q = 0; q < 4; q++) {
            int idx = tid + 256 * q;
            int r = idx >> 5, c = idx & 31;
            Ft[r][c] = F[(ib * 32 + r) * N + kk + c];
            Xt[r][c] = X[(tb * 32 + r) * N + kk + c];
        }
        __syncthreads();
        #pragma unroll
        for (int k = 0; k < 32; k++) {
            float f = Ft[il][k];
            #pragma unroll
            for (int m = 0; m < 4; m++)
                acc[m] = fmaf(f, Xt[tg + 8 * m][k], acc[m]);
        }
        __syncthreads();
    }
    #pragma unroll
    for (int m = 0; m < 4; m++)
        g_Fx[(tb * 32 + tg + 8 * m) * N + ib * 32 + il] = acc[m];
}

// ---------------- main persistent scan kernel ----------------------------
// Warp w of block b owns row b*8+w of P; lane l owns columns (k<<5)|l.
// Per step: fold col-scale while computing dots -> out -> row renorm +
// Hebbian update in regs -> block column partials (coalesced STG) ->
// sync1 -> EVERY block reduces its OWN 8-column group (4KB read) ->
// writes its c segment -> sync2 -> all read c (4KB).
__global__ __launch_bounds__(NTHR, 1) void rf_main(const float* __restrict__ X,
                                                   float* __restrict__ out) {
    __shared__ float c_s[N];
    __shared__ float x_s[N];
    __shared__ float slice[8][N];   // 32 KB
    __shared__ float red8[8][8];

    const int tid = threadIdx.x;
    const int w = tid >> 5;
    const int l = tid & 31;
    const int blk = blockIdx.x;
    const int row = blk * 8 + w;

    float Q[32];
    #pragma unroll
    for (int k = 0; k < 32; k++) Q[k] = 0.0f;

    for (int j = tid; j < N; j += NTHR) { x_s[j] = X[j]; c_s[j] = 1.0f; }
    __syncthreads();

    for (int t = 0; t < T; t++) {
        const float fxv = g_Fx[t * N + row];   // broadcast within warp

        // ---- fold column scale, dot1 = P@x, dot2 = sum(P) ---------------
        float dot1 = 0.0f, dot2 = 0.0f;
        #pragma unroll
        for (int k = 0; k < 32; k++) {
            int j = (k << 5) | l;
            float p = Q[k] * c_s[j];
            Q[k] = p;
            dot1 = fmaf(p, x_s[j], dot1);
            dot2 += p;
        }
        #pragma unroll
        for (int o = 16; o; o >>= 1) {
            dot1 += __shfl_xor_sync(0xFFFFFFFFu, dot1, o);
            dot2 += __shfl_xor_sync(0xFFFFFFFFu, dot2, o);
        }

        const float outv = fxv + dot1;
        if (l == 0) out[t * N + row] = outv;
        if (t == T - 1) break;

        // ---- row renorm + Hebbian update in registers -------------------
        float rowsum = dot2 + LMBDA * outv * g_Sx[t];
        float r = (rowsum > 1.0f) ? (1.0f / rowsum) : 1.0f;
        float ra = r * LMBDA * outv;
        #pragma unroll
        for (int k = 0; k < 32; k++) {
            int j = (k << 5) | l;
            Q[k] = fmaf(ra, x_s[j], r * Q[k]);
            slice[w][j] = Q[k];
        }
        __syncthreads();

        // ---- block column partials: coalesced STG.128 -------------------
        {
            float4 a = make_float4(0.f, 0.f, 0.f, 0.f);
            #pragma unroll
            for (int ww = 0; ww < 8; ww++) {
                float4 v = *reinterpret_cast<const float4*>(&slice[ww][tid * 4]);
                a.x += v.x; a.y += v.y; a.z += v.z; a.w += v.w;
            }
            // element e = tid*4+q -> group e/8 = tid>>1, blk slot, half (tid&1)*4
            *reinterpret_cast<float4*>(
                &g_part[((tid >> 1) * NBLK + blk) * 8 + (tid & 1) * 4]) = a;
        }
        __syncthreads();                       // all partial STGs issued
        if (tid == 0) red_release_gpu(&g_cnt1, 1u);

        // ---- overlap: stage x_{t+1} while stragglers finish -------------
        for (int j = tid; j < N; j += NTHR) x_s[j] = X[(t + 1) * N + j];

        if (tid == 0) {
            const unsigned tgt = (unsigned)NBLK * (unsigned)(t + 1);
            while (ld_acquire_gpu(&g_cnt1) < tgt) { }
        }
        __syncthreads();

        // ---- reduce OWN group (4 KB, fully coalesced) -------------------
        {
            const float* gp = &g_part[blk * NBLK * 8];
            float s = gp[tid] + gp[tid + 256] + gp[tid + 512] + gp[tid + 768];
            // thread tid holds (blk-chunk b = tid/8 + 32k, column tid%8)
            s += __shfl_xor_sync(0xFFFFFFFFu, s, 16);
            s += __shfl_xor_sync(0xFFFFFFFFu, s, 8);
            if (l < 8) red8[w][l] = s;
        }
        __syncthreads();
        if (tid < 8) {
            float s = red8[0][tid] + red8[1][tid] + red8[2][tid] + red8[3][tid]
                    + red8[4][tid] + red8[5][tid] + red8[6][tid] + red8[7][tid];
            g_c[blk * 8 + tid] = (s > 1.0f) ? (1.0f / s) : 1.0f;
        }
        __syncthreads();                       // c segment stores issued
        if (tid == 0) {
            red_release_gpu(&g_cnt2, 1u);
            const unsigned tgt = (unsigned)NBLK * (unsigned)(t + 1);
            while (ld_acquire_gpu(&g_cnt2) < tgt) { }
        }
        __syncthreads();

        // ---- fetch full c (4 KB) ----------------------------------------
        for (int j = tid; j < N; j += NTHR) c_s[j] = g_c[j];
        __syncthreads();
    }
}

// ---------------- launch ---------------------------------------------------
extern "C" void kernel_launch(void* const* d_in, const int* in_sizes, int n_in,
                              void* d_out, int out_size) {
    // inputs [T*N]; in_in_fixed [N*N] (dead); out_in_fixed [N*N]
    const float* X = nullptr;
    const float* F = nullptr;
    for (int i = 0; i < n_in; i++) {
        if (in_sizes[i] == T * N && X == nullptr) X = (const float*)d_in[i];
        if (in_sizes[i] == N * N) F = (const float*)d_in[i];  // last N*N = out_in_fixed
    }
    float* out = (float*)d_out;

    init_kernel<<<1, 32>>>();
    sx_kernel<<<T, 32>>>(X);
    dim3 g(N / 32, T / 32);
    gemm_fx<<<g, 256>>>(F, X);
    rf_main<<<NBLK, NTHR>>>(X, out);
}

// round 10
// speedup vs baseline: 1.9664x; 1.1877x over previous
#include <cuda_runtime.h>
#include <cstdint>

#define T 128
#define N 1024
#define CSZ 8            // cluster size == grid size (one cluster)
#define LOCR 128         // rows/cols owned per block (N/CSZ)
#define NTHR 256
#define LMBDA 0.01f
#define PAD 129          // row pad: conflict-free row AND column passes

// ---------------- device scratch (no allocations allowed) ----------------
__device__ float g_Fx[T * N];   // precomputed F @ x_t, [t][i]
__device__ float g_Sx[T];       // precomputed sum(x_t)

// ---------------- smem layout (float offsets) ----------------------------
#define OFF_A   0                       // At[i][s], CURRENT units (16512)
#define OFF_B   (128 * PAD)             // Bt[j][s], CURRENT units (16512)
#define OFF_X   (2 * 128 * PAD)         // x_t local j slice (128)
#define OFF_FX  (OFF_X + 128)           // Fx local i slice  (128)
#define OFF_SX  (OFF_FX + 128)          // Sx[0..T)          (128)
#define OFF_U   (OFF_SX + 128)          // reduced u         (128)
#define OFF_W   (OFF_U + 128)           // reduced w         (128)
#define OFF_Z   (OFF_W + 128)           // reduced z         (128)
#define OFF_EXU (OFF_Z + 128)           // [par][half][128]  (512)
#define OFF_EXW (OFF_EXU + 512)
#define OFF_EXZ (OFF_EXW + 512)
#define SMEM_FLOATS (OFF_EXZ + 512)
#define SMEM_BYTES  (SMEM_FLOATS * 4)

// ---------------- cluster / DSMEM helpers --------------------------------
__device__ __forceinline__ uint32_t s2u(const void* p) {
    uint32_t a;
    asm("{ .reg .u64 t; cvta.to.shared.u64 t, %1; cvt.u32.u64 %0, t; }"
        : "=r"(a) : "l"(p));
    return a;
}
__device__ __forceinline__ float ld_peer(uint32_t saddr, uint32_t rank) {
    uint32_t ra; float v;
    asm volatile("mapa.shared::cluster.u32 %0, %1, %2;" : "=r"(ra) : "r"(saddr), "r"(rank));
    asm volatile("ld.shared::cluster.f32 %0, [%1];" : "=f"(v) : "r"(ra));
    return v;
}
#define CLUSTER_SYNC() do { \
    asm volatile("barrier.cluster.arrive.aligned;" ::: "memory"); \
    asm volatile("barrier.cluster.wait.aligned;"   ::: "memory"); \
} while (0)

// ---------------- prologue: Sx[t] = sum_j X[t][j] ------------------------
__global__ void sx_kernel(const float* __restrict__ X) {
    int t = blockIdx.x, l = threadIdx.x;
    float s = 0.0f;
    for (int k = l; k < N; k += 32) s += X[t * N + k];
    #pragma unroll
    for (int o = 16; o; o >>= 1) s += __shfl_xor_sync(0xFFFFFFFFu, s, o);
    if (l == 0) g_Sx[t] = s;
}

// ---------------- prologue: Fx[t][i] = sum_k F[i][k] * X[t][k] -----------
__global__ void gemm_fx(const float* __restrict__ F, const float* __restrict__ X) {
    __shared__ float Ft[32][33];
    __shared__ float Xt[32][33];
    int ib = blockIdx.x, tb = blockIdx.y;
    int tid = threadIdx.x;
    int il = tid & 31;
    int tg = tid >> 5;
    float acc[4] = {0.f, 0.f, 0.f, 0.f};
    for (int kk = 0; kk < N; kk += 32) {
        #pragma unroll
        for (int q = 0; q < 4; q++) {
            int idx = tid + 256 * q;
            int r = idx >> 5, c = idx & 31;
            Ft[r][c] = F[(ib * 32 + r) * N + kk + c];
            Xt[r][c] = X[(tb * 32 + r) * N + kk + c];
        }
        __syncthreads();
        #pragma unroll
        for (int k = 0; k < 32; k++) {
            float f = Ft[il][k];
            #pragma unroll
            for (int m = 0; m < 4; m++)
                acc[m] = fmaf(f, Xt[tg + 8 * m][k], acc[m]);
        }
        __syncthreads();
    }
    #pragma unroll
    for (int m = 0; m < 4; m++)
        g_Fx[(tb * 32 + tg + 8 * m) * N + ib * 32 + il] = acc[m];
}

// ---------------- main low-rank scan: 1 cluster of 8 blocks --------------
// P = At Bt^T exactly, both factors kept in CURRENT units; renorms are
// in-place row rescales of the owned factor rows. Per step t:
//  B phase (thread j): colsum_j = sum_s Bt[j,s] z_s  (z = A col sums after
//    step t-1 row renorm => col sums of row-renormed P). If >1 scale
//    Bt[j,:] by 1/colsum (completes step t-1 col renorm). Append Bt[j,t]=x_j.
//  u_s = sum_j Bt[j,s] x_j, w_s = sum_j Bt[j,s]  (s<t)  -> DSMEM all-reduce
//  A phase (thread i): out_i = Fx_i + sum_s At[i,s] u_s. Append
//    At[i,t] = lambda*out_i. rowsum = sum_s At[i,s] w_s + lambda*out_i*Sx.
//    If >1 scale At[i,0..t] by 1/rowsum (row renorm of updated P).
//  z_s = sum_i At[i,s] (s<=t)                          -> DSMEM all-reduce
__global__ __launch_bounds__(NTHR, 1) __cluster_dims__(CSZ, 1, 1)
void rf_lr(const float* __restrict__ X, float* __restrict__ out) {
    extern __shared__ float sm[];
    float* At = sm + OFF_A;
    float* Bt = sm + OFF_B;

    const int tid = threadIdx.x;
    const int blk = blockIdx.x;         // == cluster rank

    // zero ALL smem (defensive: nothing ever reads garbage), then load Sx
    for (int i = tid; i < SMEM_FLOATS; i += NTHR) sm[i] = 0.0f;
    __syncthreads();
    if (tid < 128) sm[OFF_SX + tid] = g_Sx[tid];
    __syncthreads();

    for (int t = 0; t < T; t++) {
        const int par = t & 1;

        // ---- stage x_t (local j) and Fx_t (local i) ---------------------
        if (tid < 128) {
            sm[OFF_X + tid]  = X[t * N + blk * LOCR + tid];
            sm[OFF_FX + tid] = g_Fx[t * N + blk * LOCR + tid];
        }
        __syncthreads();

        // ---- B phase: finish step t-1 col renorm, append col t ----------
        if (tid < 128) {
            const int j = tid;
            if (t > 0) {
                float cs = 0.0f;
                for (int s = 0; s < t; s++)
                    cs = fmaf(Bt[j * PAD + s], sm[OFF_Z + s], cs);
                if (cs > 1.0f) {
                    const float c = 1.0f / cs;
                    for (int s = 0; s < t; s++) Bt[j * PAD + s] *= c;
                }
            }
            Bt[j * PAD + t] = sm[OFF_X + j];
        }
        __syncthreads();

        // ---- u,w partials (s<t), 2 threads per s ------------------------
        if (t > 0) {
            const int s = tid & 127, h = tid >> 7;
            if (s < t) {
                float up = 0.0f, wp = 0.0f;
                const int j0 = h * 64;
                for (int j = j0; j < j0 + 64; j++) {
                    const float b = Bt[j * PAD + s];
                    up = fmaf(b, sm[OFF_X + j], up);
                    wp += b;
                }
                sm[OFF_EXU + par * 256 + h * 128 + s] = up;
                sm[OFF_EXW + par * 256 + h * 128 + s] = wp;
            }
        }
        CLUSTER_SYNC();
        if (t > 0 && tid < t) {
            float u = 0.0f, w = 0.0f;
            const uint32_t au = s2u(&sm[OFF_EXU + par * 256 + tid]);
            const uint32_t aw = s2u(&sm[OFF_EXW + par * 256 + tid]);
            #pragma unroll
            for (int r0 = 0; r0 < CSZ; r0++) {
                u += ld_peer(au, r0) + ld_peer(au + 512, r0);
                w += ld_peer(aw, r0) + ld_peer(aw + 512, r0);
            }
            sm[OFF_U + tid] = u;
            sm[OFF_W + tid] = w;
        }
        __syncthreads();

        // ---- A phase: out, append, row renorm ---------------------------
        if (tid < 128) {
            const int i = tid;
            float p = 0.0f, q = 0.0f;
            for (int s = 0; s < t; s++) {
                const float a = At[i * PAD + s];
                p = fmaf(a, sm[OFF_U + s], p);
                q = fmaf(a, sm[OFF_W + s], q);
            }
            const float outv = sm[OFF_FX + i] + p;
            out[t * N + blk * LOCR + i] = outv;
            if (t < T - 1) {
                At[i * PAD + t] = LMBDA * outv;      // append in current units
                const float rs = fmaf(LMBDA * outv, sm[OFF_SX + t], q);
                if (rs > 1.0f) {
                    const float r = 1.0f / rs;
                    for (int s = 0; s <= t; s++) At[i * PAD + s] *= r;
                }
            }
        }
        if (t == T - 1) break;
        __syncthreads();

        // ---- z partials (s<=t) ------------------------------------------
        {
            const int s = tid & 127, h = tid >> 7;
            if (s <= t) {
                float zp = 0.0f;
                const int i0 = h * 64;
                for (int i = i0; i < i0 + 64; i++)
                    zp += At[i * PAD + s];
                sm[OFF_EXZ + par * 256 + h * 128 + s] = zp;
            }
        }
        CLUSTER_SYNC();
        if (tid <= t) {
            float z = 0.0f;
            const uint32_t az = s2u(&sm[OFF_EXZ + par * 256 + tid]);
            #pragma unroll
            for (int r0 = 0; r0 < CSZ; r0++)
                z += ld_peer(az, r0) + ld_peer(az + 512, r0);
            sm[OFF_Z + tid] = z;
        }
        __syncthreads();
    }
}

// ---------------- launch ---------------------------------------------------
extern "C" void kernel_launch(void* const* d_in, const int* in_sizes, int n_in,
                              void* d_out, int out_size) {
    // inputs [T*N]; in_in_fixed [N*N] (dead); out_in_fixed [N*N] (last)
    const float* X = nullptr;
    const float* F = nullptr;
    for (int i = 0; i < n_in; i++) {
        if (in_sizes[i] == T * N && X == nullptr) X = (const float*)d_in[i];
        if (in_sizes[i] == N * N) F = (const float*)d_in[i];
    }
    float* out = (float*)d_out;

    static bool attr_set = false;
    if (!attr_set) {
        cudaFuncSetAttribute(rf_lr, cudaFuncAttributeMaxDynamicSharedMemorySize,
                             SMEM_BYTES);
        attr_set = true;
    }

    sx_kernel<<<T, 32>>>(X);
    dim3 g(N / 32, T / 32);
    gemm_fx<<<g, 256>>>(F, X);
    rf_lr<<<CSZ, NTHR, SMEM_BYTES>>>(X, out);
}

// round 11
// speedup vs baseline: 1.9700x; 1.0018x over previous
#include <cuda_runtime.h>
#include <cstdint>

#define T 128
#define N 1024
#define CSZ 8            // cluster size == grid size (one cluster)
#define LOCR 128         // rows/cols owned per block (N/CSZ)
#define NTHR 1024
#define LMBDA 0.01f
#define PAD 136          // 136 % 32 == 8: conflict-free for BOTH 8-lane-strided
                         // row passes and consecutive-s column passes

// ---------------- device scratch (no allocations allowed) ----------------
__device__ float g_Fx[T * N];   // precomputed F @ x_t, [t][i]
__device__ float g_Sx[T];       // precomputed sum(x_t)

// ---------------- smem layout (float offsets) ----------------------------
#define OFF_A    0                        // At[i][s]  (128*136 = 17408)
#define OFF_B    17408                    // Bt[j][s]  (17408)
#define OFF_X    34816                    // x_t local j slice (128)
#define OFF_FX   34944                    // Fx local i slice  (128)
#define OFF_SX   35072                    // Sx[0..T)          (128)
#define OFF_U    35200                    // reduced u         (128)
#define OFF_W    35328                    // reduced w         (128)
#define OFF_Z    35456                    // reduced z         (128)
#define OFF_EXU  35584                    // [8][128] u partials (1024)
#define OFF_EXW  36608                    // [8][128] w partials (1024)
#define OFF_EXZ  37632                    // [8][128] z partials (1024)
#define OFF_UW2  38656                    // [par][128] float2 (u,w) (512)
#define OFF_ZL   39168                    // [par][128] z pre-reduced (256)
#define SMEM_FLOATS 39424
#define SMEM_BYTES  (SMEM_FLOATS * 4)     // 157696 B

// ---------------- cluster / DSMEM helpers --------------------------------
__device__ __forceinline__ uint32_t s2u(const void* p) {
    uint32_t a;
    asm("{ .reg .u64 t; cvta.to.shared.u64 t, %1; cvt.u32.u64 %0, t; }"
        : "=r"(a) : "l"(p));
    return a;
}
__device__ __forceinline__ float ld_peer(uint32_t saddr, uint32_t rank) {
    uint32_t ra; float v;
    asm volatile("mapa.shared::cluster.u32 %0, %1, %2;" : "=r"(ra) : "r"(saddr), "r"(rank));
    asm volatile("ld.shared::cluster.f32 %0, [%1];" : "=f"(v) : "r"(ra));
    return v;
}
__device__ __forceinline__ float2 ld_peer_v2(uint32_t saddr, uint32_t rank) {
    uint32_t ra; float2 v;
    asm volatile("mapa.shared::cluster.u32 %0, %1, %2;" : "=r"(ra) : "r"(saddr), "r"(rank));
    asm volatile("ld.shared::cluster.v2.f32 {%0,%1}, [%2];"
                 : "=f"(v.x), "=f"(v.y) : "r"(ra));
    return v;
}
#define CLUSTER_SYNC() do { \
    asm volatile("barrier.cluster.arrive.aligned;" ::: "memory"); \
    asm volatile("barrier.cluster.wait.aligned;"   ::: "memory"); \
} while (0)

__device__ __forceinline__ float grp8_sum(float v) {
    v += __shfl_xor_sync(0xFFFFFFFFu, v, 1);
    v += __shfl_xor_sync(0xFFFFFFFFu, v, 2);
    v += __shfl_xor_sync(0xFFFFFFFFu, v, 4);
    return v;
}

// ---------------- prologue: Sx[t] = sum_j X[t][j] ------------------------
__global__ void sx_kernel(const float* __restrict__ X) {
    int t = blockIdx.x, l = threadIdx.x;
    float s = 0.0f;
    for (int k = l; k < N; k += 32) s += X[t * N + k];
    #pragma unroll
    for (int o = 16; o; o >>= 1) s += __shfl_xor_sync(0xFFFFFFFFu, s, o);
    if (l == 0) g_Sx[t] = s;
}

// ---------------- prologue: Fx[t][i] = sum_k F[i][k] * X[t][k] -----------
__global__ void gemm_fx(const float* __restrict__ F, const float* __restrict__ X) {
    __shared__ float Ft[32][33];
    __shared__ float Xt[32][33];
    int ib = blockIdx.x, tb = blockIdx.y;
    int tid = threadIdx.x;
    int il = tid & 31;
    int tg = tid >> 5;
    float acc[4] = {0.f, 0.f, 0.f, 0.f};
    for (int kk = 0; kk < N; kk += 32) {
        #pragma unroll
        for (int q = 0; q < 4; q++) {
            int idx = tid + 256 * q;
            int r = idx >> 5, c = idx & 31;
            Ft[r][c] = F[(ib * 32 + r) * N + kk + c];
            Xt[r][c] = X[(tb * 32 + r) * N + kk + c];
        }
        __syncthreads();
        #pragma unroll
        for (int k = 0; k < 32; k++) {
            float f = Ft[il][k];
            #pragma unroll
            for (int m = 0; m < 4; m++)
                acc[m] = fmaf(f, Xt[tg + 8 * m][k], acc[m]);
        }
        __syncthreads();
    }
    #pragma unroll
    for (int m = 0; m < 4; m++)
        g_Fx[(tb * 32 + tg + 8 * m) * N + ib * 32 + il] = acc[m];
}

// ---------------- main low-rank scan: 1 cluster of 8 blocks, 1024 thr ----
// P = At Bt^T exactly, factors in CURRENT units; renorms = in-place row
// rescales. 8 threads per factor row (strided s, shfl group-reduce).
__global__ __launch_bounds__(NTHR, 1) __cluster_dims__(CSZ, 1, 1)
void rf_lr(const float* __restrict__ X, float* __restrict__ out) {
    extern __shared__ float sm[];
    float* At = sm + OFF_A;
    float* Bt = sm + OFF_B;

    const int tid = threadIdx.x;
    const int blk = blockIdx.x;         // == cluster rank
    const int rr  = tid >> 3;           // row (0..127) in row phases
    const int sub = tid & 7;            // sub-lane within row group
    const int sc  = tid & 127;          // s index in column phases
    const int h   = tid >> 7;           // slice (0..7) in column phases

    // zero ALL smem (nothing ever reads garbage), load Sx
    for (int i = tid; i < SMEM_FLOATS; i += NTHR) sm[i] = 0.0f;
    __syncthreads();
    if (tid < 128) sm[OFF_SX + tid] = g_Sx[tid];

    // prefetch x_0 / Fx_0
    float x_n = 0.0f, fx_n = 0.0f;
    if (tid < 128) {
        x_n  = X[blk * LOCR + tid];
        fx_n = g_Fx[blk * LOCR + tid];
    }
    __syncthreads();

    for (int t = 0; t < T; t++) {
        const int par = t & 1;

        // ---- stage prefetched x_t / Fx_t, issue prefetch for t+1 --------
        if (tid < 128) {
            sm[OFF_X + tid]  = x_n;
            sm[OFF_FX + tid] = fx_n;
        }
        __syncthreads();
        if (t + 1 < T && tid < 128) {
            x_n  = X[(t + 1) * N + blk * LOCR + tid];
            fx_n = g_Fx[(t + 1) * N + blk * LOCR + tid];
        }

        // ---- B phase: finish step t-1 col renorm, append col t ----------
        {
            if (t > 0) {
                float cs = 0.0f;
                for (int s = sub; s < t; s += 8)
                    cs = fmaf(Bt[rr * PAD + s], sm[OFF_Z + s], cs);
                cs = grp8_sum(cs);
                if (cs > 1.0f) {
                    const float c = 1.0f / cs;
                    for (int s = sub; s < t; s += 8) Bt[rr * PAD + s] *= c;
                }
            }
            if (sub == 0) Bt[rr * PAD + t] = sm[OFF_X + rr];
        }
        __syncthreads();

        // ---- u,w partials (8 slices of 16 j each) -----------------------
        if (t > 0 && sc < t) {
            float up = 0.0f, wp = 0.0f;
            const int j0 = h * 16;
            #pragma unroll 4
            for (int j = j0; j < j0 + 16; j++) {
                const float b = Bt[j * PAD + sc];
                up = fmaf(b, sm[OFF_X + j], up);
                wp += b;
            }
            sm[OFF_EXU + h * 128 + sc] = up;
            sm[OFF_EXW + h * 128 + sc] = wp;
        }
        __syncthreads();
        if (t > 0 && tid < 128) {
            float u = 0.0f, w = 0.0f;
            #pragma unroll
            for (int hh = 0; hh < 8; hh++) {
                u += sm[OFF_EXU + hh * 128 + tid];
                w += sm[OFF_EXW + hh * 128 + tid];
            }
            *reinterpret_cast<float2*>(&sm[OFF_UW2 + par * 256 + tid * 2]) =
                make_float2(u, w);
        }
        CLUSTER_SYNC();   // arrive has release; wait has acquire
        if (t > 0 && tid < t) {
            float u = 0.0f, w = 0.0f;
            const uint32_t a = s2u(&sm[OFF_UW2 + par * 256 + tid * 2]);
            #pragma unroll
            for (int r0 = 0; r0 < CSZ; r0++) {
                const float2 v = ld_peer_v2(a, r0);
                u += v.x; w += v.y;
            }
            sm[OFF_U + tid] = u;
            sm[OFF_W + tid] = w;
        }
        __syncthreads();

        // ---- A phase: out, append, row renorm ---------------------------
        {
            float p = 0.0f, q = 0.0f;
            for (int s = sub; s < t; s += 8) {
                const float a = At[rr * PAD + s];
                p = fmaf(a, sm[OFF_U + s], p);
                q = fmaf(a, sm[OFF_W + s], q);
            }
            p = grp8_sum(p);
            q = grp8_sum(q);
            const float outv = sm[OFF_FX + rr] + p;
            if (sub == 0) out[t * N + blk * LOCR + rr] = outv;
            if (t < T - 1) {
                const float rs = fmaf(LMBDA * outv, sm[OFF_SX + t], q);
                const float r  = (rs > 1.0f) ? (1.0f / rs) : 1.0f;
                for (int s = sub; s < t; s += 8) At[rr * PAD + s] *= r;
                if (sub == (t & 7)) At[rr * PAD + t] = r * (LMBDA * outv);
            }
        }
        if (t == T - 1) break;
        __syncthreads();

        // ---- z partials (s<=t), pre-reduce, exchange --------------------
        if (sc <= t) {
            float zp = 0.0f;
            const int i0 = h * 16;
            #pragma unroll 4
            for (int i = i0; i < i0 + 16; i++) zp += At[i * PAD + sc];
            sm[OFF_EXZ + h * 128 + sc] = zp;
        }
        __syncthreads();
        if (tid < 128) {
            float z = 0.0f;
            #pragma unroll
            for (int hh = 0; hh < 8; hh++) z += sm[OFF_EXZ + hh * 128 + tid];
            sm[OFF_ZL + par * 128 + tid] = z;
        }
        CLUSTER_SYNC();
        if (tid <= t) {
            float z = 0.0f;
            const uint32_t a = s2u(&sm[OFF_ZL + par * 128 + tid]);
            #pragma unroll
            for (int r0 = 0; r0 < CSZ; r0++) z += ld_peer(a, r0);
            sm[OFF_Z + tid] = z;
        }
        // next iteration's top __syncthreads orders Z for the B phase
    }
}

// ---------------- launch ---------------------------------------------------
extern "C" void kernel_launch(void* const* d_in, const int* in_sizes, int n_in,
                              void* d_out, int out_size) {
    // inputs [T*N]; in_in_fixed [N*N] (dead); out_in_fixed [N*N] (last)
    const float* X = nullptr;
    const float* F = nullptr;
    for (int i = 0; i < n_in; i++) {
        if (in_sizes[i] == T * N && X == nullptr) X = (const float*)d_in[i];
        if (in_sizes[i] == N * N) F = (const float*)d_in[i];
    }
    float* out = (float*)d_out;

    static bool attr_set = false;
    if (!attr_set) {
        cudaFuncSetAttribute(rf_lr, cudaFuncAttributeMaxDynamicSharedMemorySize,
                             SMEM_BYTES);
        attr_set = true;
    }

    sx_kernel<<<T, 32>>>(X);
    dim3 g(N / 32, T / 32);
    gemm_fx<<<g, 256>>>(F, X);
    rf_lr<<<CSZ, NTHR, SMEM_BYTES>>>(X, out);
}